// round 8
// baseline (speedup 1.0000x reference)
#include <cuda_runtime.h>
#include <cstdint>

// VQ-VAE time-series forward, fully fused, fp32.
// R8: single 36-tile double-buffered cp.async pipeline for all weight /
//     codebook tiles (32KB each), overlapping global loads with FFMA compute.
//     Compute paths identical to R7 (which passed at rel_err 1.6e-7).

namespace {
constexpr int kB       = 16384;
constexpr int kM       = 64;
constexpr int kThreads = 512;
constexpr int kTD      = 512;
constexpr int kHid     = 128;
constexpr int kCDim    = 64;
constexpr int kTok     = 8;
constexpr int kTiles   = 36;          // ew1:8 ew2:8 cbk:4 dw1:8 dw2:8
// smem floats: sZ[64][512] | sH[64][128] | sW[2][64][128] | sC2[512]
constexpr int kSmemFloats = kM * kTD + kM * kHid + 2 * 64 * 128 + 512; // 57856
constexpr int kSmemBytes  = kSmemFloats * 4;                           // 231424 <= 232448
}

__device__ __forceinline__ uint32_t s2u(const void* p) {
  return (uint32_t)__cvta_generic_to_shared(p);
}
__device__ __forceinline__ void cpa16(uint32_t dst, const void* src) {
  asm volatile("cp.async.cg.shared.global [%0], [%1], 16;\n" :: "r"(dst), "l"(src));
}
__device__ __forceinline__ void cpa_commit() {
  asm volatile("cp.async.commit_group;\n");
}
template <int N> __device__ __forceinline__ void cpa_wait() {
  asm volatile("cp.async.wait_group %0;\n" :: "n"(N));
}

// 32KB contiguous tile: 2048 float4, 4 per thread.
__device__ __forceinline__ void load_tile_contig(float* dstS, const float* src, int tid) {
  uint32_t d = s2u(dstS);
  #pragma unroll
  for (int i = 0; i < 4; ++i) {
    int q = tid + i * kThreads;
    cpa16(d + q * 16, src + q * 4);
  }
}
// 64 rows x 128 floats, source row stride 512 floats (ew2/dw2 N-chunks).
__device__ __forceinline__ void load_tile_strided(float* dstS, const float* src, int tid) {
  uint32_t d = s2u(dstS);
  #pragma unroll
  for (int i = 0; i < 4; ++i) {
    int q = tid + i * kThreads;          // 0..2047
    int row = q >> 5, c4 = q & 31;
    cpa16(d + q * 16, src + row * kTD + c4 * 4);
  }
}

// Global tile schedule: t -> source address class.
__device__ __forceinline__ void prefetch_tile(
    int t, float* buf, int tid,
    const float* ew1, const float* ew2, const float* cbk,
    const float* dw1, const float* dw2)
{
  if (t < 8)       load_tile_contig(buf, ew1 + t * 8192, tid);
  else if (t < 16) { int u = t - 8;  load_tile_strided(buf, ew2 + (u & 1) * 64 * kTD + (u >> 1) * 128, tid); }
  else if (t < 20) load_tile_contig(buf, cbk + (t - 16) * 8192, tid);
  else if (t < 28) load_tile_contig(buf, dw1 + (t - 20) * 8192, tid);
  else             { int u = t - 28; load_tile_strided(buf, dw2 + (u & 1) * 64 * kTD + (u >> 1) * 128, tid); }
  cpa_commit();
}

// C[64,128] += A[64,64-slice] * B[64,128]; 4x4 micro-tile.
__device__ __forceinline__ void gemm64(const float* __restrict__ sA, int lda,
                                       const float* __restrict__ sB,
                                       int r0, int c0, float (&acc)[4][4])
{
  #pragma unroll 4
  for (int kk = 0; kk < 64; kk += 4) {
    float4 av[4], bv[4];
    #pragma unroll
    for (int i = 0; i < 4; ++i)
      av[i] = *reinterpret_cast<const float4*>(sA + (r0 + i) * lda + kk);
    #pragma unroll
    for (int j = 0; j < 4; ++j)
      bv[j] = *reinterpret_cast<const float4*>(sB + (kk + j) * 128 + c0);
    #pragma unroll
    for (int i = 0; i < 4; ++i) {
      acc[i][0] = fmaf(av[i].x, bv[0].x, acc[i][0]);
      acc[i][1] = fmaf(av[i].x, bv[0].y, acc[i][1]);
      acc[i][2] = fmaf(av[i].x, bv[0].z, acc[i][2]);
      acc[i][3] = fmaf(av[i].x, bv[0].w, acc[i][3]);
      acc[i][0] = fmaf(av[i].y, bv[1].x, acc[i][0]);
      acc[i][1] = fmaf(av[i].y, bv[1].y, acc[i][1]);
      acc[i][2] = fmaf(av[i].y, bv[1].z, acc[i][2]);
      acc[i][3] = fmaf(av[i].y, bv[1].w, acc[i][3]);
      acc[i][0] = fmaf(av[i].z, bv[2].x, acc[i][0]);
      acc[i][1] = fmaf(av[i].z, bv[2].y, acc[i][1]);
      acc[i][2] = fmaf(av[i].z, bv[2].z, acc[i][2]);
      acc[i][3] = fmaf(av[i].z, bv[2].w, acc[i][3]);
      acc[i][0] = fmaf(av[i].w, bv[3].x, acc[i][0]);
      acc[i][1] = fmaf(av[i].w, bv[3].y, acc[i][1]);
      acc[i][2] = fmaf(av[i].w, bv[3].z, acc[i][2]);
      acc[i][3] = fmaf(av[i].w, bv[3].w, acc[i][3]);
    }
  }
}

// One pipeline step header: prefetch t+1, drain so tile t is resident, sync.
#define PIPE_HEAD(t)                                                        \
  do {                                                                      \
    if ((t) + 1 < kTiles) {                                                 \
      prefetch_tile((t) + 1, sWb[((t) + 1) & 1], tid, ew1, ew2, cbk, dw1, dw2); \
      cpa_wait<1>();                                                        \
    } else {                                                                \
      cpa_wait<0>();                                                        \
    }                                                                       \
    __syncthreads();                                                        \
  } while (0)

__global__ void __launch_bounds__(kThreads, 1)
vqvae_fused(const float* __restrict__ x,
            const float* __restrict__ ew1, const float* __restrict__ eb1,
            const float* __restrict__ ew2, const float* __restrict__ eb2,
            const float* __restrict__ cbk,
            const float* __restrict__ dw1, const float* __restrict__ db1,
            const float* __restrict__ dw2, const float* __restrict__ db2,
            float* __restrict__ out, long long out_size)
{
  extern __shared__ float smem[];
  float* sZ  = smem;                    // [64][512] x -> z_e -> z_q
  float* sH  = sZ + kM * kTD;           // [64][128]
  float* sW0 = sH + kM * kHid;          // [64][128] buffer 0
  float* sW1 = sW0 + 64 * 128;          // [64][128] buffer 1
  float* sC2 = sW1 + 64 * 128;          // [512] ||c||^2 (fp64-accumulated)
  float* sWb[2] = { sW0, sW1 };

  const int tid = threadIdx.x;
  const int b0  = blockIdx.x * kM;
  const int r0  = (tid >> 5) * 4;
  const int c0  = (tid & 31) * 4;

  // group 0: X tile (128KB) + weight tile 0
  {
    uint32_t d = s2u(sZ);
    const float* xs = x + (size_t)b0 * kTD;
    #pragma unroll
    for (int i = 0; i < 16; ++i) {
      int q = tid + i * kThreads;
      cpa16(d + q * 16, xs + q * 4);
    }
    load_tile_contig(sW0, ew1, tid);
    cpa_commit();
  }

  float acc[4][4];
  #pragma unroll
  for (int i = 0; i < 4; ++i)
    #pragma unroll
    for (int j = 0; j < 4; ++j) acc[i][j] = 0.f;

  // ---------------- GEMM1: h = relu(X @ enc_w1 + b1), tiles 0..7 ----------------
  for (int t = 0; t < 8; ++t) {
    PIPE_HEAD(t);
    gemm64(sZ + t * 64, kTD, sWb[t & 1], r0, c0, acc);
    __syncthreads();
  }
  #pragma unroll
  for (int i = 0; i < 4; ++i)
    #pragma unroll
    for (int j = 0; j < 4; ++j) {
      float v = acc[i][j] + __ldg(&eb1[c0 + j]);
      sH[(r0 + i) * kHid + c0 + j] = fmaxf(v, 0.f);
    }

  // ---------------- GEMM2: z_e = h @ enc_w2 + b2, tiles 8..15 ----------------
  for (int t = 8; t < 16; ++t) {
    const int u = t - 8, nc = u >> 1, kt = u & 1;
    PIPE_HEAD(t);
    if (kt == 0) {
      #pragma unroll
      for (int i = 0; i < 4; ++i)
        #pragma unroll
        for (int j = 0; j < 4; ++j) acc[i][j] = 0.f;
    }
    gemm64(sH + kt * 64, kHid, sWb[t & 1], r0, c0, acc);
    if (kt == 1) {
      const int n0 = nc * 128;
      #pragma unroll
      for (int i = 0; i < 4; ++i)
        #pragma unroll
        for (int j = 0; j < 4; ++j)
          sZ[(r0 + i) * kTD + n0 + c0 + j] = acc[i][j] + __ldg(&eb2[n0 + c0 + j]);
    }
    __syncthreads();
  }

  // ---------------- LayerNorm (per token-instance) + c2 precompute ----------------
  const int row = tid >> 3;
  const int tok = tid & 7;
  float* zp = sZ + row * kTD + tok * kCDim;

  float4 zf[16];
  float mu = 0.f;
  #pragma unroll
  for (int j = 0; j < 16; ++j) {
    zf[j] = reinterpret_cast<const float4*>(zp)[j];
    mu += (zf[j].x + zf[j].y) + (zf[j].z + zf[j].w);
  }
  mu *= (1.f / 64.f);
  float var = 0.f;
  #pragma unroll
  for (int j = 0; j < 16; ++j) {
    float dx = zf[j].x - mu, dy = zf[j].y - mu, dz = zf[j].z - mu, dw = zf[j].w - mu;
    var += (dx * dx + dy * dy) + (dz * dz + dw * dw);
  }
  var *= (1.f / 64.f);
  const float rs = rsqrtf(var + 1e-5f);
  #pragma unroll
  for (int j = 0; j < 16; ++j) {
    zf[j].x = (zf[j].x - mu) * rs;
    zf[j].y = (zf[j].y - mu) * rs;
    zf[j].z = (zf[j].z - mu) * rs;
    zf[j].w = (zf[j].w - mu) * rs;
  }
  {
    // ||c||^2 for code `tid`, fp64 accumulation (error ~4e-6) from global
    double s = 0.0;
    const float4* cr = reinterpret_cast<const float4*>(cbk + tid * kCDim);
    #pragma unroll
    for (int j = 0; j < 16; ++j) {
      float4 v = __ldg(&cr[j]);
      s += (double)v.x * v.x + (double)v.y * v.y +
           (double)v.z * v.z + (double)v.w * v.w;
    }
    sC2[tid] = (float)s;
  }

  // ---------------- VQ argmin of c2[k]-2*dot[k], tiles 16..19 ----------------
  float best = 3.402823466e38f;
  int bidx = 0;
  for (int t = 16; t < 20; ++t) {
    PIPE_HEAD(t);                       // sync also publishes sC2 / LN writes
    const float* cb = sWb[t & 1];
    const int g0 = (t - 16) * 128;
    #pragma unroll 2
    for (int c = 0; c < 128; ++c) {
      const float4* cr = reinterpret_cast<const float4*>(cb + c * kCDim);
      float p[16];
      #pragma unroll
      for (int j = 0; j < 16; ++j) {
        float4 cv = cr[j];              // warp-uniform broadcast
        float tt = zf[j].x * cv.x;
        tt = fmaf(zf[j].y, cv.y, tt);
        tt = fmaf(zf[j].z, cv.z, tt);
        tt = fmaf(zf[j].w, cv.w, tt);
        p[j] = tt;
      }
      #pragma unroll
      for (int s = 8; s >= 1; s >>= 1)
        #pragma unroll
        for (int j = 0; j < 16; ++j)
          if (j < s) p[j] = p[j] + p[j + s];
      const float dist = fmaf(-2.f, p[0], sC2[g0 + c]);
      if (dist < best) { best = dist; bidx = g0 + c; }  // strict < == first-min
    }
    __syncthreads();
  }

  // gather + straight-through; write z_q and indices
  {
    const float4* cr = reinterpret_cast<const float4*>(cbk + bidx * kCDim);
    const bool wZ = out_size >= 2LL * kB * kTD;
    float* ozq = out + (size_t)kB * kTD + (size_t)(b0 + row) * kTD + tok * kCDim;
    #pragma unroll
    for (int j = 0; j < 16; ++j) {
      float4 cv = __ldg(&cr[j]);
      float4 zq;
      zq.x = zf[j].x + (cv.x - zf[j].x);
      zq.y = zf[j].y + (cv.y - zf[j].y);
      zq.z = zf[j].z + (cv.z - zf[j].z);
      zq.w = zf[j].w + (cv.w - zf[j].w);
      reinterpret_cast<float4*>(zp)[j] = zq;
      if (wZ) reinterpret_cast<float4*>(ozq)[j] = zq;
    }
    if (out_size >= 2LL * kB * kTD + (long long)kB * kTok)
      out[(size_t)2 * kB * kTD + (size_t)(b0 + row) * kTok + tok] = (float)bidx;
  }

  // ---------------- GEMM3: h2 = relu(z_q @ dec_w1 + b1), tiles 20..27 ----------------
  #pragma unroll
  for (int i = 0; i < 4; ++i)
    #pragma unroll
    for (int j = 0; j < 4; ++j) acc[i][j] = 0.f;

  for (int t = 20; t < 28; ++t) {
    PIPE_HEAD(t);                       // sync also publishes z_q writes to sZ
    gemm64(sZ + (t - 20) * 64, kTD, sWb[t & 1], r0, c0, acc);
    __syncthreads();
  }
  #pragma unroll
  for (int i = 0; i < 4; ++i)
    #pragma unroll
    for (int j = 0; j < 4; ++j) {
      float v = acc[i][j] + __ldg(&db1[c0 + j]);
      sH[(r0 + i) * kHid + c0 + j] = fmaxf(v, 0.f);
    }

  // ---------------- GEMM4: recon = h2 @ dec_w2 + b2 -> gmem, tiles 28..35 ----------------
  for (int t = 28; t < 36; ++t) {
    const int u = t - 28, nc = u >> 1, kt = u & 1;
    PIPE_HEAD(t);
    if (kt == 0) {
      #pragma unroll
      for (int i = 0; i < 4; ++i)
        #pragma unroll
        for (int j = 0; j < 4; ++j) acc[i][j] = 0.f;
    }
    gemm64(sH + kt * 64, kHid, sWb[t & 1], r0, c0, acc);
    if (kt == 1) {
      const int n0 = nc * 128;
      #pragma unroll
      for (int i = 0; i < 4; ++i) {
        float4 o;
        o.x = acc[i][0] + __ldg(&db2[n0 + c0 + 0]);
        o.y = acc[i][1] + __ldg(&db2[n0 + c0 + 1]);
        o.z = acc[i][2] + __ldg(&db2[n0 + c0 + 2]);
        o.w = acc[i][3] + __ldg(&db2[n0 + c0 + 3]);
        *reinterpret_cast<float4*>(out + (size_t)(b0 + r0 + i) * kTD + n0 + c0) = o;
      }
    }
    __syncthreads();
  }
}

extern "C" void kernel_launch(void* const* d_in, const int* in_sizes, int n_in,
                              void* d_out, int out_size)
{
  const float* x   = (const float*)d_in[0];
  const float* ew1 = (const float*)d_in[1];
  const float* eb1 = (const float*)d_in[2];
  const float* ew2 = (const float*)d_in[3];
  const float* eb2 = (const float*)d_in[4];
  const float* cbk = (const float*)d_in[5];
  const float* dw1 = (const float*)d_in[6];
  const float* db1 = (const float*)d_in[7];
  const float* dw2 = (const float*)d_in[8];
  const float* db2 = (const float*)d_in[9];

  cudaFuncSetAttribute(vqvae_fused,
                       cudaFuncAttributeMaxDynamicSharedMemorySize, kSmemBytes);
  vqvae_fused<<<kB / kM, kThreads, kSmemBytes>>>(
      x, ew1, eb1, ew2, eb2, cbk, dw1, db1, dw2, db2,
      (float*)d_out, (long long)out_size);
}

// round 9
// speedup vs baseline: 1.5159x; 1.5159x over previous
#include <cuda_runtime.h>
#include <cstdint>

// VQ-VAE time-series forward, fully fused, fp32 semantics via packed f32x2.
// R9: R7 structure (proven 630us) with fma.rn.f32x2 inner loops:
//     2 IEEE fp32 FMAs per issue slot. GEMM accumulator chains keep R7's
//     exact per-lane order -> GEMM results bit-identical to R7.

namespace {
constexpr int kB       = 16384;
constexpr int kM       = 64;
constexpr int kThreads = 512;
constexpr int kTD      = 512;
constexpr int kHid     = 128;
constexpr int kCDim    = 64;
constexpr int kTok     = 8;
constexpr int kSmemFloats = kM * kTD + kM * kHid + 128 * 128 + 256;   // 57600
constexpr int kSmemBytes  = kSmemFloats * 4;                          // 230400
}

using ull = unsigned long long;

__device__ __forceinline__ ull dup2(float a) {
  ull r;
  asm("mov.b64 %0, {%1, %1};" : "=l"(r) : "f"(a));
  return r;
}
__device__ __forceinline__ void fma2(ull& d, ull a, ull b) {
  asm("fma.rn.f32x2 %0, %1, %2, %0;" : "+l"(d) : "l"(a), "l"(b));
}
__device__ __forceinline__ ull add2(ull a, ull b) {
  ull d;
  asm("add.rn.f32x2 %0, %1, %2;" : "=l"(d) : "l"(a), "l"(b));
  return d;
}
__device__ __forceinline__ float2 unpack2(ull v) {
  float2 f;
  asm("mov.b64 {%0, %1}, %2;" : "=f"(f.x), "=f"(f.y) : "l"(v));
  return f;
}

union F4U2 { float4 f; ulonglong2 u; };

// C[64,128] += A[64,128] * B[128,128]; 4 rows x (2 f32x2) per thread.
// Per-accumulator-lane fma order identical to the scalar R7 kernel.
__device__ __forceinline__ void gemm128(const float* __restrict__ sA, int lda,
                                        const float* __restrict__ sB,
                                        int r0, int c0, ull (&acc)[4][2])
{
  #pragma unroll 4
  for (int kk = 0; kk < 128; kk += 4) {
    float4 av[4];
    ulonglong2 bv[4];
    #pragma unroll
    for (int i = 0; i < 4; ++i)
      av[i] = *reinterpret_cast<const float4*>(sA + (r0 + i) * lda + kk);
    #pragma unroll
    for (int j = 0; j < 4; ++j)
      bv[j] = *reinterpret_cast<const ulonglong2*>(sB + (kk + j) * 128 + c0);
    #pragma unroll
    for (int k = 0; k < 4; ++k) {
      #pragma unroll
      for (int i = 0; i < 4; ++i) {
        const float a = reinterpret_cast<const float*>(&av[i])[k];
        const ull ad = dup2(a);
        fma2(acc[i][0], ad, bv[k].x);
        fma2(acc[i][1], ad, bv[k].y);
      }
    }
  }
}

__global__ void __launch_bounds__(kThreads, 1)
vqvae_fused(const float* __restrict__ x,
            const float* __restrict__ ew1, const float* __restrict__ eb1,
            const float* __restrict__ ew2, const float* __restrict__ eb2,
            const float* __restrict__ cbk,
            const float* __restrict__ dw1, const float* __restrict__ db1,
            const float* __restrict__ dw2, const float* __restrict__ db2,
            float* __restrict__ out, long long out_size)
{
  extern __shared__ float smem[];
  float* sZ  = smem;                    // [64][512] x -> z_e -> z_q
  float* sH  = sZ + kM * kTD;           // [64][128]
  float* sW  = sH + kM * kHid;          // [128][128] weight / codebook tile
  float* sC2 = sW + 128 * 128;          // [256] ||c||^2 (fp64-accumulated)

  const int tid = threadIdx.x;
  const int b0  = blockIdx.x * kM;
  const int r0  = (tid >> 5) * 4;
  const int c0  = (tid & 31) * 4;

  // ---------------- load X tile [64,512] ----------------
  {
    const float4* src = reinterpret_cast<const float4*>(x + (size_t)b0 * kTD);
    float4* dst = reinterpret_cast<float4*>(sZ);
    #pragma unroll
    for (int i = 0; i < 16; ++i)
      dst[tid + i * kThreads] = src[tid + i * kThreads];
  }

  ull acc[4][2];

  // ---------------- GEMM1: h = relu(X @ enc_w1 + b1) ----------------
  #pragma unroll
  for (int i = 0; i < 4; ++i) { acc[i][0] = 0ull; acc[i][1] = 0ull; }

  for (int kt = 0; kt < 4; ++kt) {
    __syncthreads();
    const float4* src = reinterpret_cast<const float4*>(ew1 + kt * 128 * kHid);
    float4* dst = reinterpret_cast<float4*>(sW);
    #pragma unroll
    for (int i = 0; i < 8; ++i)
      dst[tid + i * kThreads] = src[tid + i * kThreads];
    __syncthreads();
    gemm128(sZ + kt * 128, kTD, sW, r0, c0, acc);
  }
  #pragma unroll
  for (int i = 0; i < 4; ++i) {
    float2 p0 = unpack2(acc[i][0]);
    float2 p1 = unpack2(acc[i][1]);
    sH[(r0 + i) * kHid + c0 + 0] = fmaxf(p0.x + __ldg(&eb1[c0 + 0]), 0.f);
    sH[(r0 + i) * kHid + c0 + 1] = fmaxf(p0.y + __ldg(&eb1[c0 + 1]), 0.f);
    sH[(r0 + i) * kHid + c0 + 2] = fmaxf(p1.x + __ldg(&eb1[c0 + 2]), 0.f);
    sH[(r0 + i) * kHid + c0 + 3] = fmaxf(p1.y + __ldg(&eb1[c0 + 3]), 0.f);
  }

  // ---------------- GEMM2: z_e = h @ enc_w2 + b2 (4 N-chunks) ----------------
  for (int nc = 0; nc < 4; ++nc) {
    const int n0 = nc * 128;
    __syncthreads();
    #pragma unroll
    for (int q = tid; q < 4096; q += kThreads) {
      const int k = q >> 5, j4 = q & 31;
      reinterpret_cast<float4*>(sW)[q] =
          *reinterpret_cast<const float4*>(ew2 + k * kTD + n0 + j4 * 4);
    }
    __syncthreads();
    #pragma unroll
    for (int i = 0; i < 4; ++i) { acc[i][0] = 0ull; acc[i][1] = 0ull; }
    gemm128(sH, kHid, sW, r0, c0, acc);
    #pragma unroll
    for (int i = 0; i < 4; ++i) {
      float2 p0 = unpack2(acc[i][0]);
      float2 p1 = unpack2(acc[i][1]);
      sZ[(r0 + i) * kTD + n0 + c0 + 0] = p0.x + __ldg(&eb2[n0 + c0 + 0]);
      sZ[(r0 + i) * kTD + n0 + c0 + 1] = p0.y + __ldg(&eb2[n0 + c0 + 1]);
      sZ[(r0 + i) * kTD + n0 + c0 + 2] = p1.x + __ldg(&eb2[n0 + c0 + 2]);
      sZ[(r0 + i) * kTD + n0 + c0 + 3] = p1.y + __ldg(&eb2[n0 + c0 + 3]);
    }
  }
  __syncthreads();

  // ---------------- LayerNorm: one token-instance per thread ----------------
  const int row = tid >> 3;
  const int tok = tid & 7;
  float* zp = sZ + row * kTD + tok * kCDim;

  F4U2 zf[16];
  float mu = 0.f;
  #pragma unroll
  for (int j = 0; j < 16; ++j) {
    zf[j].f = reinterpret_cast<const float4*>(zp)[j];
    mu += (zf[j].f.x + zf[j].f.y) + (zf[j].f.z + zf[j].f.w);
  }
  mu *= (1.f / 64.f);
  float var = 0.f;
  #pragma unroll
  for (int j = 0; j < 16; ++j) {
    float dx = zf[j].f.x - mu, dy = zf[j].f.y - mu;
    float dz = zf[j].f.z - mu, dw = zf[j].f.w - mu;
    var += (dx * dx + dy * dy) + (dz * dz + dw * dw);
  }
  var *= (1.f / 64.f);
  const float rs = rsqrtf(var + 1e-5f);
  #pragma unroll
  for (int j = 0; j < 16; ++j) {
    zf[j].f.x = (zf[j].f.x - mu) * rs;
    zf[j].f.y = (zf[j].f.y - mu) * rs;
    zf[j].f.z = (zf[j].f.z - mu) * rs;
    zf[j].f.w = (zf[j].f.w - mu) * rs;
  }

  // ---------------- VQ argmin of c2[k] - 2*dot[k] ----------------
  float best = 3.402823466e38f;
  int bidx = 0;
  for (int pass = 0; pass < 2; ++pass) {
    __syncthreads();
    {  // codebook tile: 256 codes x 64 (contiguous 64KB)
      const float4* src = reinterpret_cast<const float4*>(cbk + pass * 256 * kCDim);
      float4* dst = reinterpret_cast<float4*>(sW);
      #pragma unroll
      for (int i = 0; i < 8; ++i)
        dst[tid + i * kThreads] = src[tid + i * kThreads];
    }
    __syncthreads();
    if (tid < 256) {
      double s = 0.0;
      const float4* cr = reinterpret_cast<const float4*>(sW + tid * kCDim);
      #pragma unroll
      for (int j = 0; j < 16; ++j) {
        float4 v = cr[j];
        s += (double)v.x * v.x + (double)v.y * v.y +
             (double)v.z * v.z + (double)v.w * v.w;
      }
      sC2[tid] = (float)s;
    }
    __syncthreads();
    #pragma unroll 2
    for (int c = 0; c < 256; ++c) {
      const ulonglong2* cr = reinterpret_cast<const ulonglong2*>(sW + c * kCDim);
      // 4 parallel f32x2 chains (8 deep), then f32x2 tree + cross add.
      ull s0 = 0ull, s1 = 0ull, s2 = 0ull, s3 = 0ull;
      #pragma unroll
      for (int j = 0; j < 16; j += 2) {
        ulonglong2 ca = cr[j];       // warp-uniform broadcast LDS.128
        ulonglong2 cb2 = cr[j + 1];
        fma2(s0, zf[j].u.x, ca.x);
        fma2(s1, zf[j].u.y, ca.y);
        fma2(s2, zf[j + 1].u.x, cb2.x);
        fma2(s3, zf[j + 1].u.y, cb2.y);
      }
      ull t = add2(add2(s0, s1), add2(s2, s3));
      float2 d2 = unpack2(t);
      const float dot  = d2.x + d2.y;
      const float dist = fmaf(-2.f, dot, sC2[c]);
      const int g = pass * 256 + c;
      if (dist < best) { best = dist; bidx = g; }   // strict < == first-min
    }
  }

  // gather + straight-through; write z_q and indices
  {
    const float4* cr = reinterpret_cast<const float4*>(cbk + bidx * kCDim);
    const bool wZ = out_size >= 2LL * kB * kTD;
    float* ozq = out + (size_t)kB * kTD + (size_t)(b0 + row) * kTD + tok * kCDim;
    #pragma unroll
    for (int j = 0; j < 16; ++j) {
      float4 cv = __ldg(&cr[j]);
      float4 zq;
      zq.x = zf[j].f.x + (cv.x - zf[j].f.x);
      zq.y = zf[j].f.y + (cv.y - zf[j].f.y);
      zq.z = zf[j].f.z + (cv.z - zf[j].f.z);
      zq.w = zf[j].f.w + (cv.w - zf[j].f.w);
      reinterpret_cast<float4*>(zp)[j] = zq;
      if (wZ) reinterpret_cast<float4*>(ozq)[j] = zq;
    }
    if (out_size >= 2LL * kB * kTD + (long long)kB * kTok)
      out[(size_t)2 * kB * kTD + (size_t)(b0 + row) * kTok + tok] = (float)bidx;
  }

  // ---------------- GEMM3: h2 = relu(z_q @ dec_w1 + b1) ----------------
  #pragma unroll
  for (int i = 0; i < 4; ++i) { acc[i][0] = 0ull; acc[i][1] = 0ull; }

  for (int kt = 0; kt < 4; ++kt) {
    __syncthreads();
    const float4* src = reinterpret_cast<const float4*>(dw1 + kt * 128 * kHid);
    float4* dst = reinterpret_cast<float4*>(sW);
    #pragma unroll
    for (int i = 0; i < 8; ++i)
      dst[tid + i * kThreads] = src[tid + i * kThreads];
    __syncthreads();
    gemm128(sZ + kt * 128, kTD, sW, r0, c0, acc);
  }
  #pragma unroll
  for (int i = 0; i < 4; ++i) {
    float2 p0 = unpack2(acc[i][0]);
    float2 p1 = unpack2(acc[i][1]);
    sH[(r0 + i) * kHid + c0 + 0] = fmaxf(p0.x + __ldg(&db1[c0 + 0]), 0.f);
    sH[(r0 + i) * kHid + c0 + 1] = fmaxf(p0.y + __ldg(&db1[c0 + 1]), 0.f);
    sH[(r0 + i) * kHid + c0 + 2] = fmaxf(p1.x + __ldg(&db1[c0 + 2]), 0.f);
    sH[(r0 + i) * kHid + c0 + 3] = fmaxf(p1.y + __ldg(&db1[c0 + 3]), 0.f);
  }

  // ---------------- GEMM4: recon = h2 @ dec_w2 + b2 -> gmem ----------------
  for (int nc = 0; nc < 4; ++nc) {
    const int n0 = nc * 128;
    __syncthreads();
    #pragma unroll
    for (int q = tid; q < 4096; q += kThreads) {
      const int k = q >> 5, j4 = q & 31;
      reinterpret_cast<float4*>(sW)[q] =
          *reinterpret_cast<const float4*>(dw2 + k * kTD + n0 + j4 * 4);
    }
    __syncthreads();
    #pragma unroll
    for (int i = 0; i < 4; ++i) { acc[i][0] = 0ull; acc[i][1] = 0ull; }
    gemm128(sH, kHid, sW, r0, c0, acc);
    #pragma unroll
    for (int i = 0; i < 4; ++i) {
      float2 p0 = unpack2(acc[i][0]);
      float2 p1 = unpack2(acc[i][1]);
      float4 o;
      o.x = p0.x + __ldg(&db2[n0 + c0 + 0]);
      o.y = p0.y + __ldg(&db2[n0 + c0 + 1]);
      o.z = p1.x + __ldg(&db2[n0 + c0 + 2]);
      o.w = p1.y + __ldg(&db2[n0 + c0 + 3]);
      *reinterpret_cast<float4*>(out + (size_t)(b0 + r0 + i) * kTD + n0 + c0) = o;
    }
  }
}

extern "C" void kernel_launch(void* const* d_in, const int* in_sizes, int n_in,
                              void* d_out, int out_size)
{
  const float* x   = (const float*)d_in[0];
  const float* ew1 = (const float*)d_in[1];
  const float* eb1 = (const float*)d_in[2];
  const float* ew2 = (const float*)d_in[3];
  const float* eb2 = (const float*)d_in[4];
  const float* cbk = (const float*)d_in[5];
  const float* dw1 = (const float*)d_in[6];
  const float* db1 = (const float*)d_in[7];
  const float* dw2 = (const float*)d_in[8];
  const float* db2 = (const float*)d_in[9];

  cudaFuncSetAttribute(vqvae_fused,
                       cudaFuncAttributeMaxDynamicSharedMemorySize, kSmemBytes);
  vqvae_fused<<<kB / kM, kThreads, kSmemBytes>>>(
      x, ew1, eb1, ew2, eb2, cbk, dw1, db1, dw2, db2,
      (float*)d_out, (long long)out_size);
}

// round 10
// speedup vs baseline: 1.8085x; 1.1930x over previous
#include <cuda_runtime.h>
#include <cstdint>

// VQ-VAE time-series forward, fully fused, fp32 semantics via packed f32x2.
// R10: 256 threads, 8x4 micro-tile (halves smem-crossbar B traffic per FMA,
//      which R9's ncu showed as the binding resource: L1=74%). Dual-instance
//      VQ per thread (both z vectors resident in registers). All accumulation
//      orders identical to R9 -> bit-identical results.

namespace {
constexpr int kB       = 16384;
constexpr int kM       = 64;
constexpr int kThreads = 256;
constexpr int kTD      = 512;
constexpr int kHid     = 128;
constexpr int kCDim    = 64;
constexpr int kTok     = 8;
constexpr int kSmemFloats = kM * kTD + kM * kHid + 128 * 128 + 256;   // 57600
constexpr int kSmemBytes  = kSmemFloats * 4;                          // 230400
}

using ull = unsigned long long;

__device__ __forceinline__ ull dup2(float a) {
  ull r;
  asm("mov.b64 %0, {%1, %1};" : "=l"(r) : "f"(a));
  return r;
}
__device__ __forceinline__ void fma2(ull& d, ull a, ull b) {
  asm("fma.rn.f32x2 %0, %1, %2, %0;" : "+l"(d) : "l"(a), "l"(b));
}
__device__ __forceinline__ ull add2(ull a, ull b) {
  ull d;
  asm("add.rn.f32x2 %0, %1, %2;" : "=l"(d) : "l"(a), "l"(b));
  return d;
}
__device__ __forceinline__ float2 unpack2(ull v) {
  float2 f;
  asm("mov.b64 {%0, %1}, %2;" : "=f"(f.x), "=f"(f.y) : "l"(v));
  return f;
}

union F4U2 { float4 f; ulonglong2 u; };

// C[64,128] += A[64,128] * B[128,128]; 8 rows x (2 f32x2) per thread.
// Per-accumulator-lane fma order identical to R9 (bit-identical results).
__device__ __forceinline__ void gemm128(const float* __restrict__ sA, int lda,
                                        const float* __restrict__ sB,
                                        int r0, int c0, ull (&acc)[8][2])
{
  #pragma unroll 4
  for (int kk = 0; kk < 128; kk += 4) {
    float4 av[8];
    ulonglong2 bv[4];
    #pragma unroll
    for (int i = 0; i < 8; ++i)
      av[i] = *reinterpret_cast<const float4*>(sA + (r0 + i) * lda + kk);
    #pragma unroll
    for (int j = 0; j < 4; ++j)
      bv[j] = *reinterpret_cast<const ulonglong2*>(sB + (kk + j) * 128 + c0);
    #pragma unroll
    for (int k = 0; k < 4; ++k) {
      #pragma unroll
      for (int i = 0; i < 8; ++i) {
        const float a = reinterpret_cast<const float*>(&av[i])[k];
        const ull ad = dup2(a);
        fma2(acc[i][0], ad, bv[k].x);
        fma2(acc[i][1], ad, bv[k].y);
      }
    }
  }
}

// LayerNorm of a 64-float vector held as 16 float4 in registers.
__device__ __forceinline__ void ln64(F4U2 (&zf)[16]) {
  float mu = 0.f;
  #pragma unroll
  for (int j = 0; j < 16; ++j)
    mu += (zf[j].f.x + zf[j].f.y) + (zf[j].f.z + zf[j].f.w);
  mu *= (1.f / 64.f);
  float var = 0.f;
  #pragma unroll
  for (int j = 0; j < 16; ++j) {
    float dx = zf[j].f.x - mu, dy = zf[j].f.y - mu;
    float dz = zf[j].f.z - mu, dw = zf[j].f.w - mu;
    var += (dx * dx + dy * dy) + (dz * dz + dw * dw);
  }
  var *= (1.f / 64.f);
  const float rs = rsqrtf(var + 1e-5f);
  #pragma unroll
  for (int j = 0; j < 16; ++j) {
    zf[j].f.x = (zf[j].f.x - mu) * rs;
    zf[j].f.y = (zf[j].f.y - mu) * rs;
    zf[j].f.z = (zf[j].f.z - mu) * rs;
    zf[j].f.w = (zf[j].f.w - mu) * rs;
  }
}

__global__ void __launch_bounds__(kThreads, 1)
vqvae_fused(const float* __restrict__ x,
            const float* __restrict__ ew1, const float* __restrict__ eb1,
            const float* __restrict__ ew2, const float* __restrict__ eb2,
            const float* __restrict__ cbk,
            const float* __restrict__ dw1, const float* __restrict__ db1,
            const float* __restrict__ dw2, const float* __restrict__ db2,
            float* __restrict__ out, long long out_size)
{
  extern __shared__ float smem[];
  float* sZ  = smem;                    // [64][512] x -> z_e -> z_q
  float* sH  = sZ + kM * kTD;           // [64][128]
  float* sW  = sH + kM * kHid;          // [128][128] weight / codebook tile
  float* sC2 = sW + 128 * 128;          // [256] ||c||^2 per pass (fp64-acc)

  const int tid = threadIdx.x;
  const int b0  = blockIdx.x * kM;
  const int r0  = (tid >> 5) * 8;       // 8 warps x 8 rows = 64
  const int c0  = (tid & 31) * 4;

  // ---------------- load X tile [64,512] ----------------
  {
    const float4* src = reinterpret_cast<const float4*>(x + (size_t)b0 * kTD);
    float4* dst = reinterpret_cast<float4*>(sZ);
    #pragma unroll
    for (int i = 0; i < 32; ++i)
      dst[tid + i * kThreads] = src[tid + i * kThreads];
  }

  ull acc[8][2];

  // ---------------- GEMM1: h = relu(X @ enc_w1 + b1) ----------------
  #pragma unroll
  for (int i = 0; i < 8; ++i) { acc[i][0] = 0ull; acc[i][1] = 0ull; }

  for (int kt = 0; kt < 4; ++kt) {
    __syncthreads();
    const float4* src = reinterpret_cast<const float4*>(ew1 + kt * 128 * kHid);
    float4* dst = reinterpret_cast<float4*>(sW);
    #pragma unroll
    for (int i = 0; i < 16; ++i)
      dst[tid + i * kThreads] = src[tid + i * kThreads];
    __syncthreads();
    gemm128(sZ + kt * 128, kTD, sW, r0, c0, acc);
  }
  #pragma unroll
  for (int i = 0; i < 8; ++i) {
    float2 p0 = unpack2(acc[i][0]);
    float2 p1 = unpack2(acc[i][1]);
    sH[(r0 + i) * kHid + c0 + 0] = fmaxf(p0.x + __ldg(&eb1[c0 + 0]), 0.f);
    sH[(r0 + i) * kHid + c0 + 1] = fmaxf(p0.y + __ldg(&eb1[c0 + 1]), 0.f);
    sH[(r0 + i) * kHid + c0 + 2] = fmaxf(p1.x + __ldg(&eb1[c0 + 2]), 0.f);
    sH[(r0 + i) * kHid + c0 + 3] = fmaxf(p1.y + __ldg(&eb1[c0 + 3]), 0.f);
  }

  // ---------------- GEMM2: z_e = h @ enc_w2 + b2 (4 N-chunks) ----------------
  for (int nc = 0; nc < 4; ++nc) {
    const int n0 = nc * 128;
    __syncthreads();
    #pragma unroll
    for (int q = tid; q < 4096; q += kThreads) {
      const int k = q >> 5, j4 = q & 31;
      reinterpret_cast<float4*>(sW)[q] =
          *reinterpret_cast<const float4*>(ew2 + k * kTD + n0 + j4 * 4);
    }
    __syncthreads();
    #pragma unroll
    for (int i = 0; i < 8; ++i) { acc[i][0] = 0ull; acc[i][1] = 0ull; }
    gemm128(sH, kHid, sW, r0, c0, acc);
    #pragma unroll
    for (int i = 0; i < 8; ++i) {
      float2 p0 = unpack2(acc[i][0]);
      float2 p1 = unpack2(acc[i][1]);
      sZ[(r0 + i) * kTD + n0 + c0 + 0] = p0.x + __ldg(&eb2[n0 + c0 + 0]);
      sZ[(r0 + i) * kTD + n0 + c0 + 1] = p0.y + __ldg(&eb2[n0 + c0 + 1]);
      sZ[(r0 + i) * kTD + n0 + c0 + 2] = p1.x + __ldg(&eb2[n0 + c0 + 2]);
      sZ[(r0 + i) * kTD + n0 + c0 + 3] = p1.y + __ldg(&eb2[n0 + c0 + 3]);
    }
  }
  __syncthreads();

  // ---------------- LayerNorm: two token-instances per thread ----------------
  // instance A = tid (rows 0..31), instance B = tid + 256 (rows 32..63)
  const int rowA = tid >> 3,        tokA = tid & 7;
  const int rowB = 32 + (tid >> 3), tokB = tid & 7;
  float* zpA = sZ + rowA * kTD + tokA * kCDim;
  float* zpB = sZ + rowB * kTD + tokB * kCDim;

  F4U2 zfA[16], zfB[16];
  #pragma unroll
  for (int j = 0; j < 16; ++j) zfA[j].f = reinterpret_cast<const float4*>(zpA)[j];
  #pragma unroll
  for (int j = 0; j < 16; ++j) zfB[j].f = reinterpret_cast<const float4*>(zpB)[j];
  ln64(zfA);
  ln64(zfB);

  // ---------------- VQ argmin of c2[k] - 2*dot[k], both instances ----------------
  float bestA = 3.402823466e38f, bestB = 3.402823466e38f;
  int bidxA = 0, bidxB = 0;
  for (int pass = 0; pass < 2; ++pass) {
    __syncthreads();
    {  // codebook tile: 256 codes x 64 (contiguous 64KB)
      const float4* src = reinterpret_cast<const float4*>(cbk + pass * 256 * kCDim);
      float4* dst = reinterpret_cast<float4*>(sW);
      #pragma unroll
      for (int i = 0; i < 16; ++i)
        dst[tid + i * kThreads] = src[tid + i * kThreads];
    }
    __syncthreads();
    {
      // ||c||^2 for code `tid` of this tile, fp64 accumulation (error ~4e-6)
      double s = 0.0;
      const float4* cr = reinterpret_cast<const float4*>(sW + tid * kCDim);
      #pragma unroll
      for (int j = 0; j < 16; ++j) {
        float4 v = cr[j];
        s += (double)v.x * v.x + (double)v.y * v.y +
             (double)v.z * v.z + (double)v.w * v.w;
      }
      sC2[tid] = (float)s;
    }
    __syncthreads();
    for (int c = 0; c < 256; ++c) {
      const ulonglong2* cr = reinterpret_cast<const ulonglong2*>(sW + c * kCDim);
      // 4 parallel f32x2 chains per instance; same order as R9.
      ull a0 = 0ull, a1 = 0ull, a2 = 0ull, a3 = 0ull;
      ull b0v = 0ull, b1v = 0ull, b2v = 0ull, b3v = 0ull;
      #pragma unroll
      for (int j = 0; j < 16; j += 2) {
        ulonglong2 ca = cr[j];       // warp-uniform broadcast LDS.128
        ulonglong2 cb2 = cr[j + 1];
        fma2(a0, zfA[j].u.x, ca.x);
        fma2(a1, zfA[j].u.y, ca.y);
        fma2(a2, zfA[j + 1].u.x, cb2.x);
        fma2(a3, zfA[j + 1].u.y, cb2.y);
        fma2(b0v, zfB[j].u.x, ca.x);
        fma2(b1v, zfB[j].u.y, ca.y);
        fma2(b2v, zfB[j + 1].u.x, cb2.x);
        fma2(b3v, zfB[j + 1].u.y, cb2.y);
      }
      const float c2v = sC2[c];
      const int g = pass * 256 + c;
      {
        ull t = add2(add2(a0, a1), add2(a2, a3));
        float2 d2 = unpack2(t);
        const float dist = fmaf(-2.f, d2.x + d2.y, c2v);
        if (dist < bestA) { bestA = dist; bidxA = g; }   // strict < == first-min
      }
      {
        ull t = add2(add2(b0v, b1v), add2(b2v, b3v));
        float2 d2 = unpack2(t);
        const float dist = fmaf(-2.f, d2.x + d2.y, c2v);
        if (dist < bestB) { bestB = dist; bidxB = g; }
      }
    }
  }

  // gather + straight-through; write z_q and indices (both instances)
  {
    const bool wZ = out_size >= 2LL * kB * kTD;
    const bool wI = out_size >= 2LL * kB * kTD + (long long)kB * kTok;
    #pragma unroll
    for (int inst = 0; inst < 2; ++inst) {
      const int row = inst ? rowB : rowA;
      const int tok = inst ? tokB : tokA;
      const int bidx = inst ? bidxB : bidxA;
      F4U2* zf = inst ? zfB : zfA;
      float* zp = inst ? zpB : zpA;
      const float4* cr = reinterpret_cast<const float4*>(cbk + bidx * kCDim);
      float* ozq = out + (size_t)kB * kTD + (size_t)(b0 + row) * kTD + tok * kCDim;
      #pragma unroll
      for (int j = 0; j < 16; ++j) {
        float4 cv = __ldg(&cr[j]);
        float4 zq;
        zq.x = zf[j].f.x + (cv.x - zf[j].f.x);
        zq.y = zf[j].f.y + (cv.y - zf[j].f.y);
        zq.z = zf[j].f.z + (cv.z - zf[j].f.z);
        zq.w = zf[j].f.w + (cv.w - zf[j].f.w);
        reinterpret_cast<float4*>(zp)[j] = zq;
        if (wZ) reinterpret_cast<float4*>(ozq)[j] = zq;
      }
      if (wI)
        out[(size_t)2 * kB * kTD + (size_t)(b0 + row) * kTok + tok] = (float)bidx;
    }
  }

  // ---------------- GEMM3: h2 = relu(z_q @ dec_w1 + b1) ----------------
  #pragma unroll
  for (int i = 0; i < 8; ++i) { acc[i][0] = 0ull; acc[i][1] = 0ull; }

  for (int kt = 0; kt < 4; ++kt) {
    __syncthreads();                    // also publishes z_q writes to sZ
    const float4* src = reinterpret_cast<const float4*>(dw1 + kt * 128 * kHid);
    float4* dst = reinterpret_cast<float4*>(sW);
    #pragma unroll
    for (int i = 0; i < 16; ++i)
      dst[tid + i * kThreads] = src[tid + i * kThreads];
    __syncthreads();
    gemm128(sZ + kt * 128, kTD, sW, r0, c0, acc);
  }
  #pragma unroll
  for (int i = 0; i < 8; ++i) {
    float2 p0 = unpack2(acc[i][0]);
    float2 p1 = unpack2(acc[i][1]);
    sH[(r0 + i) * kHid + c0 + 0] = fmaxf(p0.x + __ldg(&db1[c0 + 0]), 0.f);
    sH[(r0 + i) * kHid + c0 + 1] = fmaxf(p0.y + __ldg(&db1[c0 + 1]), 0.f);
    sH[(r0 + i) * kHid + c0 + 2] = fmaxf(p1.x + __ldg(&db1[c0 + 2]), 0.f);
    sH[(r0 + i) * kHid + c0 + 3] = fmaxf(p1.y + __ldg(&db1[c0 + 3]), 0.f);
  }

  // ---------------- GEMM4: recon = h2 @ dec_w2 + b2 -> gmem ----------------
  for (int nc = 0; nc < 4; ++nc) {
    const int n0 = nc * 128;
    __syncthreads();
    #pragma unroll
    for (int q = tid; q < 4096; q += kThreads) {
      const int k = q >> 5, j4 = q & 31;
      reinterpret_cast<float4*>(sW)[q] =
          *reinterpret_cast<const float4*>(dw2 + k * kTD + n0 + j4 * 4);
    }
    __syncthreads();
    #pragma unroll
    for (int i = 0; i < 8; ++i) { acc[i][0] = 0ull; acc[i][1] = 0ull; }
    gemm128(sH, kHid, sW, r0, c0, acc);
    #pragma unroll
    for (int i = 0; i < 8; ++i) {
      float2 p0 = unpack2(acc[i][0]);
      float2 p1 = unpack2(acc[i][1]);
      float4 o;
      o.x = p0.x + __ldg(&db2[n0 + c0 + 0]);
      o.y = p0.y + __ldg(&db2[n0 + c0 + 1]);
      o.z = p1.x + __ldg(&db2[n0 + c0 + 2]);
      o.w = p1.y + __ldg(&db2[n0 + c0 + 3]);
      *reinterpret_cast<float4*>(out + (size_t)(b0 + r0 + i) * kTD + n0 + c0) = o;
    }
  }
}

extern "C" void kernel_launch(void* const* d_in, const int* in_sizes, int n_in,
                              void* d_out, int out_size)
{
  const float* x   = (const float*)d_in[0];
  const float* ew1 = (const float*)d_in[1];
  const float* eb1 = (const float*)d_in[2];
  const float* ew2 = (const float*)d_in[3];
  const float* eb2 = (const float*)d_in[4];
  const float* cbk = (const float*)d_in[5];
  const float* dw1 = (const float*)d_in[6];
  const float* db1 = (const float*)d_in[7];
  const float* dw2 = (const float*)d_in[8];
  const float* db2 = (const float*)d_in[9];

  cudaFuncSetAttribute(vqvae_fused,
                       cudaFuncAttributeMaxDynamicSharedMemorySize, kSmemBytes);
  vqvae_fused<<<kB / kM, kThreads, kSmemBytes>>>(
      x, ew1, eb1, ew2, eb2, cbk, dw1, db1, dw2, db2,
      (float*)d_out, (long long)out_size);
}